// round 6
// baseline (speedup 1.0000x reference)
#include <cuda_runtime.h>
#include <cstdint>

// upfirdn2d, UP=1, DOWN=2, PAD=5, separable sym6 (12 taps), fp32.
// Vertical-first from global (coalesced float2 column strips, register ring),
// horizontal from smem. y[i,j] = sum_q HR[q] * tmpV[i][2j+q-5].

#define IMG_H   256
#define IMG_W   256
#define OUT_H   128
#define OUT_W   128
#define O_ROWS  64
#define STRIDE  276           // floats; 276 % 32 = 20 -> low-conflict phase H
#define PADL    8             // left zero pad; data words [8, 264)
#define NT      512

#define HR0  ( 0.015404109327027373f)
#define HR1  ( 0.0034907120842174702f)
#define HR2  (-0.11799011114819057f)
#define HR3  (-0.048311742585633f)
#define HR4  ( 0.4910559419267466f)
#define HR5  ( 0.787641141030194f)
#define HR6  ( 0.3379294217276218f)
#define HR7  (-0.07263752278646252f)
#define HR8  (-0.021060292512300564f)
#define HR9  ( 0.04472490177066578f)
#define HR10 ( 0.0017677118642428036f)
#define HR11 (-0.007800708325034148f)

__device__ __forceinline__ float tap12(const float* w) {
    float a;
    a = HR0 * w[0];
    a = fmaf(HR1,  w[1],  a);
    a = fmaf(HR2,  w[2],  a);
    a = fmaf(HR3,  w[3],  a);
    a = fmaf(HR4,  w[4],  a);
    a = fmaf(HR5,  w[5],  a);
    a = fmaf(HR6,  w[6],  a);
    a = fmaf(HR7,  w[7],  a);
    a = fmaf(HR8,  w[8],  a);
    a = fmaf(HR9,  w[9],  a);
    a = fmaf(HR10, w[10], a);
    a = fmaf(HR11, w[11], a);
    return a;
}

__device__ __forceinline__ float2 tap12v(const float2* w) {
    float2 a;
    a.x = HR0 * w[0].x;            a.y = HR0 * w[0].y;
    a.x = fmaf(HR1,  w[1].x, a.x); a.y = fmaf(HR1,  w[1].y, a.y);
    a.x = fmaf(HR2,  w[2].x, a.x); a.y = fmaf(HR2,  w[2].y, a.y);
    a.x = fmaf(HR3,  w[3].x, a.x); a.y = fmaf(HR3,  w[3].y, a.y);
    a.x = fmaf(HR4,  w[4].x, a.x); a.y = fmaf(HR4,  w[4].y, a.y);
    a.x = fmaf(HR5,  w[5].x, a.x); a.y = fmaf(HR5,  w[5].y, a.y);
    a.x = fmaf(HR6,  w[6].x, a.x); a.y = fmaf(HR6,  w[6].y, a.y);
    a.x = fmaf(HR7,  w[7].x, a.x); a.y = fmaf(HR7,  w[7].y, a.y);
    a.x = fmaf(HR8,  w[8].x, a.x); a.y = fmaf(HR8,  w[8].y, a.y);
    a.x = fmaf(HR9,  w[9].x, a.x); a.y = fmaf(HR9,  w[9].y, a.y);
    a.x = fmaf(HR10, w[10].x, a.x); a.y = fmaf(HR10, w[10].y, a.y);
    a.x = fmaf(HR11, w[11].x, a.x); a.y = fmaf(HR11, w[11].y, a.y);
    return a;
}

// Vertical pass for one 16-output-row strip of 2 columns.
// CHECK=false: all 42 input rows in range -> raw loads, no predicates.
template<bool CHECK>
__device__ __forceinline__ void vpass(const float2* __restrict__ colp,
                                      float* __restrict__ sdst, int g0)
{
    float2 w[12];
    #pragma unroll
    for (int t = 0; t < 10; t++) {
        int g = g0 + t;
        if (CHECK && (unsigned)g >= (unsigned)IMG_H) w[t] = make_float2(0.f, 0.f);
        else                                         w[t] = __ldg(colp + g * (IMG_W / 2));
    }
    #pragma unroll
    for (int i = 0; i < 16; i++) {
        int gA = g0 + 2 * i + 10;
        int gB = gA + 1;
        if (CHECK && (unsigned)gA >= (unsigned)IMG_H) w[10] = make_float2(0.f, 0.f);
        else                                          w[10] = __ldg(colp + gA * (IMG_W / 2));
        if (CHECK && (unsigned)gB >= (unsigned)IMG_H) w[11] = make_float2(0.f, 0.f);
        else                                          w[11] = __ldg(colp + gB * (IMG_W / 2));

        float2 o = tap12v(w);
        *reinterpret_cast<float2*>(sdst + i * STRIDE) = o;

        #pragma unroll
        for (int k = 0; k < 10; k++) w[k] = w[k + 2];
    }
}

// Horizontal chunk: 8 stride-2 outputs from a 32-word aligned smem window.
// base = &tmpV[il*STRIDE + woff]; outputs d=0..7 read words [2d+3, 2d+14].
__device__ __forceinline__ void hchunk(const float* __restrict__ base,
                                       float* __restrict__ dst)
{
    float v[32];
    #pragma unroll
    for (int m = 0; m < 8; m++) {
        float4 q = *reinterpret_cast<const float4*>(base + 4 * m);
        v[4 * m + 0] = q.x;
        v[4 * m + 1] = q.y;
        v[4 * m + 2] = q.z;
        v[4 * m + 3] = q.w;
    }
    #pragma unroll
    for (int s = 0; s < 2; s++) {
        float4 q;
        q.x = tap12(&v[2 * (4 * s + 0) + 3]);
        q.y = tap12(&v[2 * (4 * s + 1) + 3]);
        q.z = tap12(&v[2 * (4 * s + 2) + 3]);
        q.w = tap12(&v[2 * (4 * s + 3) + 3]);
        *reinterpret_cast<float4*>(dst + 4 * s) = q;
    }
}

__global__ void __launch_bounds__(NT, 3)
hp_sym6_v4(const float* __restrict__ in, float* __restrict__ out)
{
    extern __shared__ float tmpV[];   // [O_ROWS][STRIDE]

    const int ty  = blockIdx.x;       // tile within image (fastest -> L2 halo reuse)
    const int img = blockIdx.y;
    const int tid = threadIdx.x;
    const int i0  = ty * O_ROWS;

    const float* __restrict__ src = in + (size_t)img * (IMG_H * IMG_W);

    // zero pad columns: words [0,8) and [264,276) of each tmpV row
    #pragma unroll
    for (int z = tid; z < O_ROWS * 20; z += NT) {
        int rr = z / 20;
        int pz = z - rr * 20;
        tmpV[rr * STRIDE + (pz < 8 ? pz : 256 + pz)] = 0.0f;
    }

    // ---- Phase V: 4 strips x 16 output rows, 2 columns (float2) per thread ----
    {
        const int h  = tid >> 7;            // strip 0..3
        const int c2 = (tid & 127) * 2;     // column pair
        const int g0 = 2 * (i0 + h * 16) - 5;
        const float2* colp = reinterpret_cast<const float2*>(src + c2);
        float* sdst = &tmpV[(h * 16) * STRIDE + PADL + c2];

        if (g0 >= 0 && g0 + 41 < IMG_H) vpass<false>(colp, sdst, g0);
        else                            vpass<true >(colp, sdst, g0);
    }
    __syncthreads();

    // ---- Phase H: 12-tap stride-2 from smem; 2 chunks of 8 outputs/thread ----
    {
        const int wid  = tid >> 5;          // 0..15
        const int lane = tid & 31;
        const int c8   = lane >> 2;         // 0..7 -> 16 output cols each
        const int isub = lane & 3;
        const int il   = 4 * wid + isub;    // local output row 0..63

        const float* rowv = &tmpV[il * STRIDE + 32 * c8];
        float* __restrict__ dst =
            out + (size_t)img * (OUT_H * OUT_W) + (i0 + il) * OUT_W + 16 * c8;

        // chunk 0: outputs 0..7  (reads words [3,17] of window)
        hchunk(rowv, dst);
        // chunk 1: outputs 8..15 (same formula shifted 16 words / 8 outputs)
        hchunk(rowv + 16, dst + 8);
    }
}

extern "C" void kernel_launch(void* const* d_in, const int* in_sizes, int n_in,
                              void* d_out, int out_size)
{
    const float* x = (const float*)d_in[0];
    float* y = (float*)d_out;

    int n_img = in_sizes[0] / (IMG_H * IMG_W);            // 1024
    size_t smem = (size_t)O_ROWS * STRIDE * sizeof(float); // 70656 B

    cudaFuncSetAttribute(hp_sym6_v4,
                         cudaFuncAttributeMaxDynamicSharedMemorySize, (int)smem);

    dim3 grid(OUT_H / O_ROWS, n_img);   // (2, 1024): tiles fastest for L2 reuse
    hp_sym6_v4<<<grid, NT, smem>>>(x, y);
}

// round 7
// speedup vs baseline: 1.2059x; 1.2059x over previous
#include <cuda_runtime.h>
#include <cstdint>

// upfirdn2d, UP=1, DOWN=2, PAD=5, separable sym6 (12 taps), fp32.
// Vertical-first from global with FRONT-BATCHED loads (26 independent float2
// loads per 8-row block -> high MLP), horizontal from smem.

#define IMG_H   256
#define IMG_W   256
#define OUT_H   128
#define OUT_W   128
#define O_ROWS  64
#define STRIDE  276           // floats; 276 % 32 = 20 -> low-conflict phase H
#define PADL    8             // left zero pad; data words [8, 264)
#define NT      512

#define HR0  ( 0.015404109327027373f)
#define HR1  ( 0.0034907120842174702f)
#define HR2  (-0.11799011114819057f)
#define HR3  (-0.048311742585633f)
#define HR4  ( 0.4910559419267466f)
#define HR5  ( 0.787641141030194f)
#define HR6  ( 0.3379294217276218f)
#define HR7  (-0.07263752278646252f)
#define HR8  (-0.021060292512300564f)
#define HR9  ( 0.04472490177066578f)
#define HR10 ( 0.0017677118642428036f)
#define HR11 (-0.007800708325034148f)

__device__ __forceinline__ float tap12(const float* w) {
    float a;
    a = HR0 * w[0];
    a = fmaf(HR1,  w[1],  a);
    a = fmaf(HR2,  w[2],  a);
    a = fmaf(HR3,  w[3],  a);
    a = fmaf(HR4,  w[4],  a);
    a = fmaf(HR5,  w[5],  a);
    a = fmaf(HR6,  w[6],  a);
    a = fmaf(HR7,  w[7],  a);
    a = fmaf(HR8,  w[8],  a);
    a = fmaf(HR9,  w[9],  a);
    a = fmaf(HR10, w[10], a);
    a = fmaf(HR11, w[11], a);
    return a;
}

__device__ __forceinline__ float2 tap12v(const float2* w) {
    float2 a;
    a.x = HR0 * w[0].x;            a.y = HR0 * w[0].y;
    a.x = fmaf(HR1,  w[1].x, a.x); a.y = fmaf(HR1,  w[1].y, a.y);
    a.x = fmaf(HR2,  w[2].x, a.x); a.y = fmaf(HR2,  w[2].y, a.y);
    a.x = fmaf(HR3,  w[3].x, a.x); a.y = fmaf(HR3,  w[3].y, a.y);
    a.x = fmaf(HR4,  w[4].x, a.x); a.y = fmaf(HR4,  w[4].y, a.y);
    a.x = fmaf(HR5,  w[5].x, a.x); a.y = fmaf(HR5,  w[5].y, a.y);
    a.x = fmaf(HR6,  w[6].x, a.x); a.y = fmaf(HR6,  w[6].y, a.y);
    a.x = fmaf(HR7,  w[7].x, a.x); a.y = fmaf(HR7,  w[7].y, a.y);
    a.x = fmaf(HR8,  w[8].x, a.x); a.y = fmaf(HR8,  w[8].y, a.y);
    a.x = fmaf(HR9,  w[9].x, a.x); a.y = fmaf(HR9,  w[9].y, a.y);
    a.x = fmaf(HR10, w[10].x, a.x); a.y = fmaf(HR10, w[10].y, a.y);
    a.x = fmaf(HR11, w[11].x, a.x); a.y = fmaf(HR11, w[11].y, a.y);
    return a;
}

// Vertical pass, one 8-output-row block of 2 columns.
// All 26 input-row loads are issued up front (independent -> MLP ~26).
template<bool CHECK>
__device__ __forceinline__ void vpass8(const float2* __restrict__ colp,
                                       float* __restrict__ sdst, int g0)
{
    float2 w[26];
    #pragma unroll
    for (int t = 0; t < 26; t++) {
        int g = g0 + t;
        if (CHECK && (unsigned)g >= (unsigned)IMG_H) w[t] = make_float2(0.f, 0.f);
        else                                         w[t] = __ldg(colp + g * (IMG_W / 2));
    }
    #pragma unroll
    for (int i = 0; i < 8; i++) {
        float2 o = tap12v(&w[2 * i]);
        *reinterpret_cast<float2*>(sdst + i * STRIDE) = o;
    }
}

__global__ void __launch_bounds__(NT, 2)
hp_sym6_v5(const float* __restrict__ in, float* __restrict__ out)
{
    extern __shared__ float tmpV[];   // [O_ROWS][STRIDE]

    const int ty  = blockIdx.x;       // tile within image (fastest -> L2 halo reuse)
    const int img = blockIdx.y;
    const int tid = threadIdx.x;
    const int i0  = ty * O_ROWS;

    const float* __restrict__ src = in + (size_t)img * (IMG_H * IMG_W);

    // zero pad columns: words [0,8) and [264,276) of each tmpV row
    #pragma unroll
    for (int z = tid; z < O_ROWS * 20; z += NT) {
        int rr = z / 20;
        int pz = z - rr * 20;
        tmpV[rr * STRIDE + (pz < 8 ? pz : 256 + pz)] = 0.0f;
    }

    // ---- Phase V: 4 super-strips x (2 sub-blocks of 8 rows); 2 cols/thread ----
    {
        const int h  = tid >> 7;            // super-strip 0..3
        const int c2 = (tid & 127) * 2;     // column pair
        const float2* colp = reinterpret_cast<const float2*>(src + c2);

        #pragma unroll
        for (int sub = 0; sub < 2; sub++) {
            const int r0 = h * 16 + sub * 8;       // local output row
            const int g0 = 2 * (i0 + r0) - 5;      // first input row (26 needed)
            float* sdst = &tmpV[r0 * STRIDE + PADL + c2];

            if (g0 >= 0 && g0 + 25 < IMG_H) vpass8<false>(colp, sdst, g0);
            else                            vpass8<true >(colp, sdst, g0);
        }
    }
    __syncthreads();

    // ---- Phase H: 12-tap stride-2 from smem, 16 outputs per thread ----
    {
        const int wid  = tid >> 5;          // 0..15
        const int lane = tid & 31;
        const int c8   = lane >> 2;         // 0..7 -> 16 output cols each
        const int isub = lane & 3;
        const int il   = 4 * wid + isub;    // local output row 0..63

        const float* rowv = &tmpV[il * STRIDE + 32 * c8];
        float v[48];
        #pragma unroll
        for (int m = 0; m < 12; m++) {
            float4 q = *reinterpret_cast<const float4*>(rowv + 4 * m);
            v[4 * m + 0] = q.x;
            v[4 * m + 1] = q.y;
            v[4 * m + 2] = q.z;
            v[4 * m + 3] = q.w;
        }

        float o[16];
        #pragma unroll
        for (int d = 0; d < 16; d++)
            o[d] = tap12(&v[2 * d + 3]);

        float* __restrict__ dst =
            out + (size_t)img * (OUT_H * OUT_W) + (i0 + il) * OUT_W + 16 * c8;
        #pragma unroll
        for (int s = 0; s < 4; s++) {
            float4 q = make_float4(o[4*s], o[4*s+1], o[4*s+2], o[4*s+3]);
            *reinterpret_cast<float4*>(dst + 4 * s) = q;
        }
    }
}

extern "C" void kernel_launch(void* const* d_in, const int* in_sizes, int n_in,
                              void* d_out, int out_size)
{
    const float* x = (const float*)d_in[0];
    float* y = (float*)d_out;

    int n_img = in_sizes[0] / (IMG_H * IMG_W);            // 1024
    size_t smem = (size_t)O_ROWS * STRIDE * sizeof(float); // 70656 B

    cudaFuncSetAttribute(hp_sym6_v5,
                         cudaFuncAttributeMaxDynamicSharedMemorySize, (int)smem);

    dim3 grid(OUT_H / O_ROWS, n_img);   // (2, 1024): tiles fastest for L2 reuse
    hp_sym6_v5<<<grid, NT, smem>>>(x, y);
}